// round 10
// baseline (speedup 1.0000x reference)
#include <cuda_runtime.h>
#include <cstdint>

// ===========================================================================
// VAE decoder, sm_103 fallback tensor path (mma.sync m16n8k8 tf32).
// All operands pre-rounded to tf32 in GMEM (vectorized cvt); GEMM mainloop is
// a 3-stage cp.async pipeline. L2's 8-expert weighted-elu sum is fused
// in-register (no per-expert output round trip).
// GEMMs: A[M,K] row * W[N,K] row^T -> C[M,N], M=4096, K%32==0.
// ===========================================================================

#define BROWS 4096
#define BM 128
#define BN 128
#define BK 32
#define LDSK 36            // pad: bank = (4r+c)%32 -> conflict-free frag loads
#define STAGES 3
#define STG_FLT (2 * BM * LDSK)        // floats per stage (A + W) = 9216
#define STG_BYTES (STG_FLT * 4)        // 36864

// ---- scratch (device globals; allocation-free) ----------------------------
__device__ float g_X  [(size_t)BROWS * 2368];            // tf32
__device__ float g_H1 [(size_t)8 * BROWS * 2048];        // tf32
__device__ float g_W1c[(size_t)8 * 2048 * 2368];         // tf32
__device__ float g_W2c[(size_t)8 * 2432 * 2048];         // tf32, N padded
__device__ float g_W3c[(size_t)2048 * 2496];
__device__ float g_W4c[(size_t)2432 * 2176];             // N padded
__device__ float g_W5c[(size_t)256 * 2496];
__device__ float g_bufC[(size_t)BROWS * 2496];           // L2 sum + z tail
__device__ float g_bufD[(size_t)BROWS * 2176];           // L3 out + z tail
__device__ float g_bufE[(size_t)BROWS * 2496];           // L4 out + z tail

// ---- helpers --------------------------------------------------------------
__device__ __forceinline__ uint32_t f2tf(float x) {
    uint32_t r; asm("cvt.rna.tf32.f32 %0, %1;" : "=r"(r) : "f"(x)); return r;
}
__device__ __forceinline__ float tfr(float x) { return __uint_as_float(f2tf(x)); }
__device__ __forceinline__ float4 tfr4(float4 v) {
    return make_float4(tfr(v.x), tfr(v.y), tfr(v.z), tfr(v.w));
}
__device__ __forceinline__ float elu1(float x) { return x > 0.f ? x : expm1f(x); }
__device__ __forceinline__ uint32_t smem_u32(const void* p) {
    uint32_t a;
    asm("{ .reg .u64 t; cvta.to.shared.u64 t, %1; cvt.u32.u64 %0, t; }" : "=r"(a) : "l"(p));
    return a;
}
__device__ __forceinline__ void cp16(uint32_t d, const void* s) {
    asm volatile("cp.async.cg.shared.global [%0], [%1], 16;" :: "r"(d), "l"(s) : "memory");
}
__device__ __forceinline__ void cp_commit() {
    asm volatile("cp.async.commit_group;" ::: "memory");
}
__device__ __forceinline__ void cp_wait1() {
    asm volatile("cp.async.wait_group 1;" ::: "memory");
}
__device__ __forceinline__ void mma_tf32(float c[4], const uint32_t a[4], const uint32_t b[2]) {
    asm volatile(
        "mma.sync.aligned.m16n8k8.row.col.f32.tf32.tf32.f32 "
        "{%0,%1,%2,%3}, {%4,%5,%6,%7}, {%8,%9}, {%0,%1,%2,%3};\n"
        : "+f"(c[0]), "+f"(c[1]), "+f"(c[2]), "+f"(c[3])
        : "r"(a[0]), "r"(a[1]), "r"(a[2]), "r"(a[3]), "r"(b[0]), "r"(b[1]));
}

// ---- prep kernels (vectorized, one row per block, no div/mod) -------------
// Weights: [E][N][K] fp32 -> [E][Npad][K] tf32. grid = (Npad, E).
__global__ void cvt_rows(const float* __restrict__ src, float* __restrict__ dst,
                         int N, int K)
{
    const int row = blockIdx.x, e = blockIdx.y;
    const int Npad = gridDim.x;
    const int n4 = K >> 2;
    float4* d = (float4*)(dst + ((size_t)e * Npad + row) * K);
    if (row < N) {
        const float4* s = (const float4*)(src + ((size_t)e * N + row) * K);
        for (int i = threadIdx.x; i < n4; i += blockDim.x) d[i] = tfr4(s[i]);
    } else {
        const float4 zz = make_float4(0.f, 0.f, 0.f, 0.f);
        for (int i = threadIdx.x; i < n4; i += blockDim.x) d[i] = zz;
    }
}

// X = tf32(concat(motions, angles, z)); z tails into bufC/D/E. grid = 4096.
__global__ void pack_kernel(const float* __restrict__ motions,
                            const float* __restrict__ angles,
                            const float* __restrict__ z)
{
    const int b = blockIdx.x;
    float4* X = (float4*)(g_X + (size_t)b * 2368);
    const float4* m4 = (const float4*)(motions + (size_t)b * 1792);
    const float4* a4 = (const float4*)(angles + (size_t)b * 448);
    const float4* z4 = (const float4*)(z + (size_t)b * 128);
    for (int i = threadIdx.x; i < 592; i += blockDim.x) {
        float4 v = (i < 448) ? m4[i] : (i < 560) ? a4[i - 448] : z4[i - 560];
        X[i] = tfr4(v);
    }
    for (int i = threadIdx.x; i < 32; i += blockDim.x) {
        float4 v = tfr4(z4[i]);
        ((float4*)(g_bufC + (size_t)b * 2496 + 2368))[i] = v;
        ((float4*)(g_bufD + (size_t)b * 2176 + 2048))[i] = v;
        ((float4*)(g_bufE + (size_t)b * 2496 + 2368))[i] = v;
    }
}

// ---- pipelined GEMM (plain / per-expert batched) --------------------------
// ROUND: tf32-round the output (feeds a later GEMM).
template<bool ROUND>
__global__ void __launch_bounds__(256, 2)
gemm_pipe(const float* __restrict__ A0, int lda, size_t sAe,
          const float* __restrict__ W0, size_t sWe,
          const float* __restrict__ bias0, int sBe,
          float* __restrict__ C0, int ldc, size_t sCe,
          int N, int K)
{
    extern __shared__ float smem[];
    const uint32_t sbase = smem_u32(smem);

    const int tid = threadIdx.x;
    const int lane = tid & 31, warp = tid >> 5;
    const int warpM = warp & 1, warpN = warp >> 1;       // 2 x 4 warps
    const int g = lane >> 2, tg = lane & 3;
    const int mBlock = blockIdx.y * BM;
    const int nBlock = blockIdx.x * BN;
    const int e = blockIdx.z;
    const int Kiters = K / BK;

    const float* A = A0 + (size_t)e * sAe;
    const float* W = W0 + (size_t)e * sWe;

    const int cr = tid >> 3;          // copy row (0..31 step via +32)
    const int cc = (tid & 7) * 16;    // byte offset in 128B row chunk

    auto issue = [&](int stage, int kt) {
        uint32_t sa = sbase + stage * STG_BYTES;
        #pragma unroll
        for (int i = 0; i < 4; i++) {
            int r = cr + i * 32;
            cp16(sa + (uint32_t)(r * (LDSK * 4)) + cc,
                 A + (size_t)(mBlock + r) * lda + kt * BK + (cc >> 2));
        }
        uint32_t sw = sa + BM * LDSK * 4;
        #pragma unroll
        for (int i = 0; i < 4; i++) {
            int r = cr + i * 32;
            cp16(sw + (uint32_t)(r * (LDSK * 4)) + cc,
                 W + (size_t)(nBlock + r) * K + kt * BK + (cc >> 2));
        }
    };

    float acc[4][4][4];
    #pragma unroll
    for (int mi = 0; mi < 4; mi++)
        #pragma unroll
        for (int ni = 0; ni < 4; ni++)
            #pragma unroll
            for (int c = 0; c < 4; c++) acc[mi][ni][c] = 0.f;

    #pragma unroll
    for (int s = 0; s < STAGES - 1; s++) {
        if (s < Kiters) issue(s, s);
        cp_commit();
    }

    const uint32_t* Asm = (const uint32_t*)smem;
    for (int kt = 0; kt < Kiters; kt++) {
        cp_wait1();
        __syncthreads();

        int nxt = kt + STAGES - 1;
        if (nxt < Kiters) issue(nxt % STAGES, nxt);
        cp_commit();

        const int st = kt % STAGES;
        const uint32_t* Ab = Asm + st * STG_FLT + (warpM * 64) * LDSK;
        const uint32_t* Wb = Asm + st * STG_FLT + BM * LDSK + (warpN * 32) * LDSK;
        #pragma unroll
        for (int ks = 0; ks < 4; ks++) {
            uint32_t af[4][4], bf[4][2];
            const int kc = ks * 8 + tg;
            #pragma unroll
            for (int mi = 0; mi < 4; mi++) {
                const uint32_t* p = Ab + (mi * 16 + g) * LDSK + kc;
                af[mi][0] = p[0];
                af[mi][1] = p[8 * LDSK];
                af[mi][2] = p[4];
                af[mi][3] = p[8 * LDSK + 4];
            }
            #pragma unroll
            for (int ni = 0; ni < 4; ni++) {
                const uint32_t* p = Wb + (ni * 8 + g) * LDSK + kc;
                bf[ni][0] = p[0];
                bf[ni][1] = p[4];
            }
            #pragma unroll
            for (int mi = 0; mi < 4; mi++)
                #pragma unroll
                for (int ni = 0; ni < 4; ni++)
                    mma_tf32(acc[mi][ni], af[mi], bf[ni]);
        }
    }

    const float* bias = bias0 + (size_t)e * sBe;
    float* C = C0 + (size_t)e * sCe;
    #pragma unroll
    for (int ni = 0; ni < 4; ni++) {
        int col0 = nBlock + warpN * 32 + ni * 8 + tg * 2;
        if (col0 >= N) continue;
        float b0 = bias[col0];
        float b1 = bias[col0 + 1];
        #pragma unroll
        for (int mi = 0; mi < 4; mi++) {
            int r0 = mBlock + warpM * 64 + mi * 16 + g;
            float y0 = elu1(acc[mi][ni][0] + b0);
            float y1 = elu1(acc[mi][ni][1] + b1);
            float y2 = elu1(acc[mi][ni][2] + b0);
            float y3 = elu1(acc[mi][ni][3] + b1);
            if (ROUND) { y0 = tfr(y0); y1 = tfr(y1); y2 = tfr(y2); y3 = tfr(y3); }
            *reinterpret_cast<float2*>(C + (size_t)r0 * ldc + col0) = make_float2(y0, y1);
            *reinterpret_cast<float2*>(C + (size_t)(r0 + 8) * ldc + col0) = make_float2(y2, y3);
        }
    }
}

// ---- pipelined GEMM with fused 8-expert weighted-elu sum (L2) -------------
// bufC[:, :N] = tf32( sum_e para[e] * elu(H1[e] @ W2[e]^T + b2[e]) )
__global__ void __launch_bounds__(256, 1)
gemm_pipe_sum(const float* __restrict__ A0, int lda, size_t sAe,
              const float* __restrict__ W0, size_t sWe,
              const float* __restrict__ bias0, int sBe,
              const float* __restrict__ para,
              float* __restrict__ C0, int ldc,
              int N, int KitersPerE, int E)
{
    extern __shared__ float smem[];
    const uint32_t sbase = smem_u32(smem);

    const int tid = threadIdx.x;
    const int lane = tid & 31, warp = tid >> 5;
    const int warpM = warp & 1, warpN = warp >> 1;
    const int g = lane >> 2, tg = lane & 3;
    const int mBlock = blockIdx.y * BM;
    const int nBlock = blockIdx.x * BN;
    const int Ktot = KitersPerE * E;

    const int cr = tid >> 3;
    const int cc = (tid & 7) * 16;

    auto issue = [&](int stage, int kt) {
        const int e = kt / KitersPerE;
        const int kk = kt - e * KitersPerE;
        const float* A = A0 + (size_t)e * sAe;
        const float* W = W0 + (size_t)e * sWe;
        uint32_t sa = sbase + stage * STG_BYTES;
        #pragma unroll
        for (int i = 0; i < 4; i++) {
            int r = cr + i * 32;
            cp16(sa + (uint32_t)(r * (LDSK * 4)) + cc,
                 A + (size_t)(mBlock + r) * lda + kk * BK + (cc >> 2));
        }
        uint32_t sw = sa + BM * LDSK * 4;
        #pragma unroll
        for (int i = 0; i < 4; i++) {
            int r = cr + i * 32;
            cp16(sw + (uint32_t)(r * (LDSK * 4)) + cc,
                 W + (size_t)(nBlock + r) * lda + kk * BK + (cc >> 2));
        }
    };

    float acc[4][4][4], sum[4][4][4];
    #pragma unroll
    for (int mi = 0; mi < 4; mi++)
        #pragma unroll
        for (int ni = 0; ni < 4; ni++)
            #pragma unroll
            for (int c = 0; c < 4; c++) { acc[mi][ni][c] = 0.f; sum[mi][ni][c] = 0.f; }

    #pragma unroll
    for (int s = 0; s < STAGES - 1; s++) { issue(s, s); cp_commit(); }

    const uint32_t* Asm = (const uint32_t*)smem;
    for (int kt = 0; kt < Ktot; kt++) {
        cp_wait1();
        __syncthreads();

        int nxt = kt + STAGES - 1;
        if (nxt < Ktot) issue(nxt % STAGES, nxt);
        cp_commit();

        const int st = kt % STAGES;
        const uint32_t* Ab = Asm + st * STG_FLT + (warpM * 64) * LDSK;
        const uint32_t* Wb = Asm + st * STG_FLT + BM * LDSK + (warpN * 32) * LDSK;
        #pragma unroll
        for (int ks = 0; ks < 4; ks++) {
            uint32_t af[4][4], bf[4][2];
            const int kc = ks * 8 + tg;
            #pragma unroll
            for (int mi = 0; mi < 4; mi++) {
                const uint32_t* p = Ab + (mi * 16 + g) * LDSK + kc;
                af[mi][0] = p[0];
                af[mi][1] = p[8 * LDSK];
                af[mi][2] = p[4];
                af[mi][3] = p[8 * LDSK + 4];
            }
            #pragma unroll
            for (int ni = 0; ni < 4; ni++) {
                const uint32_t* p = Wb + (ni * 8 + g) * LDSK + kc;
                bf[ni][0] = p[0];
                bf[ni][1] = p[4];
            }
            #pragma unroll
            for (int mi = 0; mi < 4; mi++)
                #pragma unroll
                for (int ni = 0; ni < 4; ni++)
                    mma_tf32(acc[mi][ni], af[mi], bf[ni]);
        }

        // expert boundary: fold acc -> sum, reset acc
        if ((kt + 1) % KitersPerE == 0) {
            const int e = kt / KitersPerE;
            const float pe = para[e];
            const float* bias = bias0 + (size_t)e * sBe;
            #pragma unroll
            for (int ni = 0; ni < 4; ni++) {
                int col0 = nBlock + warpN * 32 + ni * 8 + tg * 2;
                float b0 = (col0 < N)     ? bias[col0]     : 0.f;
                float b1 = (col0 + 1 < N) ? bias[col0 + 1] : 0.f;
                #pragma unroll
                for (int mi = 0; mi < 4; mi++) {
                    sum[mi][ni][0] += pe * elu1(acc[mi][ni][0] + b0);
                    sum[mi][ni][1] += pe * elu1(acc[mi][ni][1] + b1);
                    sum[mi][ni][2] += pe * elu1(acc[mi][ni][2] + b0);
                    sum[mi][ni][3] += pe * elu1(acc[mi][ni][3] + b1);
                    acc[mi][ni][0] = 0.f; acc[mi][ni][1] = 0.f;
                    acc[mi][ni][2] = 0.f; acc[mi][ni][3] = 0.f;
                }
            }
        }
    }

    #pragma unroll
    for (int ni = 0; ni < 4; ni++) {
        int col0 = nBlock + warpN * 32 + ni * 8 + tg * 2;
        if (col0 >= N) continue;
        #pragma unroll
        for (int mi = 0; mi < 4; mi++) {
            int r0 = mBlock + warpM * 64 + mi * 16 + g;
            *reinterpret_cast<float2*>(C0 + (size_t)r0 * ldc + col0) =
                make_float2(tfr(sum[mi][ni][0]), tfr(sum[mi][ni][1]));
            *reinterpret_cast<float2*>(C0 + (size_t)(r0 + 8) * ldc + col0) =
                make_float2(tfr(sum[mi][ni][2]), tfr(sum[mi][ni][3]));
        }
    }
}

// ---- launch ---------------------------------------------------------------
extern "C" void kernel_launch(void* const* d_in, const int* in_sizes, int n_in,
                              void* d_out, int out_size)
{
    const float* motions = (const float*)d_in[0];
    const float* angles  = (const float*)d_in[1];
    const float* z       = (const float*)d_in[2];
    const float* l1_w    = (const float*)d_in[3];
    const float* l1_b    = (const float*)d_in[4];
    const float* l2_w    = (const float*)d_in[5];
    const float* l2_b    = (const float*)d_in[6];
    const float* para    = (const float*)d_in[7];
    const float* l3_w    = (const float*)d_in[8];
    const float* l3_b    = (const float*)d_in[9];
    const float* l4_w    = (const float*)d_in[10];
    const float* l4_b    = (const float*)d_in[11];
    const float* l5_w    = (const float*)d_in[12];
    const float* l5_b    = (const float*)d_in[13];
    float* out = (float*)d_out;

    float *X, *H1, *W1c, *W2c, *W3c, *W4c, *W5c, *bufC, *bufD, *bufE;
    cudaGetSymbolAddress((void**)&X,    g_X);
    cudaGetSymbolAddress((void**)&H1,   g_H1);
    cudaGetSymbolAddress((void**)&W1c,  g_W1c);
    cudaGetSymbolAddress((void**)&W2c,  g_W2c);
    cudaGetSymbolAddress((void**)&W3c,  g_W3c);
    cudaGetSymbolAddress((void**)&W4c,  g_W4c);
    cudaGetSymbolAddress((void**)&W5c,  g_W5c);
    cudaGetSymbolAddress((void**)&bufC, g_bufC);
    cudaGetSymbolAddress((void**)&bufD, g_bufD);
    cudaGetSymbolAddress((void**)&bufE, g_bufE);

    const int SH = STAGES * STG_BYTES;   // 110592 B
    cudaFuncSetAttribute(gemm_pipe<true >, cudaFuncAttributeMaxDynamicSharedMemorySize, SH);
    cudaFuncSetAttribute(gemm_pipe<false>, cudaFuncAttributeMaxDynamicSharedMemorySize, SH);
    cudaFuncSetAttribute(gemm_pipe_sum,    cudaFuncAttributeMaxDynamicSharedMemorySize, SH);

    // prep: inputs + weights -> tf32 (vectorized; weights N-padded where needed)
    pack_kernel<<<4096, 256>>>(motions, angles, z);
    cvt_rows<<<dim3(2048, 8), 256>>>(l1_w, W1c, 2048, 2368);
    cvt_rows<<<dim3(2432, 8), 256>>>(l2_w, W2c, 2368, 2048);
    cvt_rows<<<dim3(2048, 1), 256>>>(l3_w, W3c, 2048, 2496);
    cvt_rows<<<dim3(2432, 1), 256>>>(l4_w, W4c, 2368, 2176);
    cvt_rows<<<dim3( 256, 1), 256>>>(l5_w, W5c,  256, 2496);

    // L1: H1[e] = tf32(elu(X @ W1[e]^T + b1[e]))   K=2368
    gemm_pipe<true><<<dim3(16, 32, 8), 256, SH>>>(
        X, 2368, (size_t)0,
        W1c, (size_t)2048 * 2368,
        l1_b, 2048,
        H1, 2048, (size_t)BROWS * 2048,
        2048, 2368);

    // L2 fused: bufC[:, :2368] = tf32(sum_e para[e]*elu(H1[e] @ W2[e]^T + b2[e]))
    gemm_pipe_sum<<<dim3(19, 32, 1), 256, SH>>>(
        H1, 2048, (size_t)BROWS * 2048,
        W2c, (size_t)2432 * 2048,
        l2_b, 2368, para,
        bufC, 2496,
        2368, 64, 8);

    // L3: bufD = tf32(elu(bufC @ W3^T + b3))   K=2496
    gemm_pipe<true><<<dim3(16, 32, 1), 256, SH>>>(
        bufC, 2496, (size_t)0, W3c, (size_t)0, l3_b, 0,
        bufD, 2176, (size_t)0, 2048, 2496);

    // L4: bufE = tf32(elu(bufD @ W4^T + b4))   K=2176, N=2368(pad 2432)
    gemm_pipe<true><<<dim3(19, 32, 1), 256, SH>>>(
        bufD, 2176, (size_t)0, W4c, (size_t)0, l4_b, 0,
        bufE, 2496, (size_t)0, 2368, 2176);

    // L5: out = elu(bufE @ W5^T + b5)   K=2496, N=256
    gemm_pipe<false><<<dim3(2, 32, 1), 256, SH>>>(
        bufE, 2496, (size_t)0, W5c, (size_t)0, l5_b, 0,
        out, 256, (size_t)0, 256, 2496);
}

// round 11
// speedup vs baseline: 1.1337x; 1.1337x over previous
#include <cuda_runtime.h>
#include <cstdint>

// ===========================================================================
// VAE decoder, sm_103 fallback tensor path (mma.sync m16n8k8 tf32).
// All operands pre-rounded to tf32 in GMEM (vectorized cvt); GEMM mainloop is
// a 3-stage cp.async pipeline, 2 CTAs/SM. L2 expert sum via per-expert planes
// + separate vectorized reduce (the in-register fold spills — measured r10).
// GEMMs: A[M,K] row * W[N,K] row^T -> C[M,N], M=4096, K%32==0.
// ===========================================================================

#define BROWS 4096
#define BM 128
#define BN 128
#define BK 32
#define LDSK 36            // pad: bank = (4r+c)%32 -> conflict-free frag loads
#define STAGES 3
#define STG_FLT (2 * BM * LDSK)        // floats per stage (A + W) = 9216
#define STG_BYTES (STG_FLT * 4)        // 36864

// ---- scratch (device globals; allocation-free) ----------------------------
__device__ float g_X  [(size_t)BROWS * 2368];            // tf32
__device__ float g_H1 [(size_t)8 * BROWS * 2048];        // tf32
__device__ float g_W1c[(size_t)8 * 2048 * 2368];         // tf32
__device__ float g_W2c[(size_t)8 * 2432 * 2048];         // tf32, N padded
__device__ float g_W3c[(size_t)2048 * 2496];
__device__ float g_W4c[(size_t)2432 * 2176];             // N padded
__device__ float g_W5c[(size_t)256 * 2496];
__device__ float g_bufC[(size_t)BROWS * 2496];           // L2 sum + z tail
__device__ float g_bufD[(size_t)BROWS * 2176];           // L3 out + z tail
__device__ float g_bufE[(size_t)BROWS * 2496];           // L4 out + z tail
__device__ float g_E2 [(size_t)8 * BROWS * 2368];        // per-expert L2 (fp32)

// ---- helpers --------------------------------------------------------------
__device__ __forceinline__ uint32_t f2tf(float x) {
    uint32_t r; asm("cvt.rna.tf32.f32 %0, %1;" : "=r"(r) : "f"(x)); return r;
}
__device__ __forceinline__ float tfr(float x) { return __uint_as_float(f2tf(x)); }
__device__ __forceinline__ float4 tfr4(float4 v) {
    return make_float4(tfr(v.x), tfr(v.y), tfr(v.z), tfr(v.w));
}
__device__ __forceinline__ float elu1(float x) { return x > 0.f ? x : expm1f(x); }
__device__ __forceinline__ uint32_t smem_u32(const void* p) {
    uint32_t a;
    asm("{ .reg .u64 t; cvta.to.shared.u64 t, %1; cvt.u32.u64 %0, t; }" : "=r"(a) : "l"(p));
    return a;
}
__device__ __forceinline__ void cp16(uint32_t d, const void* s) {
    asm volatile("cp.async.cg.shared.global [%0], [%1], 16;" :: "r"(d), "l"(s) : "memory");
}
__device__ __forceinline__ void cp_commit() {
    asm volatile("cp.async.commit_group;" ::: "memory");
}
__device__ __forceinline__ void cp_wait1() {
    asm volatile("cp.async.wait_group 1;" ::: "memory");
}
__device__ __forceinline__ void mma_tf32(float c[4], const uint32_t a[4], const uint32_t b[2]) {
    asm volatile(
        "mma.sync.aligned.m16n8k8.row.col.f32.tf32.tf32.f32 "
        "{%0,%1,%2,%3}, {%4,%5,%6,%7}, {%8,%9}, {%0,%1,%2,%3};\n"
        : "+f"(c[0]), "+f"(c[1]), "+f"(c[2]), "+f"(c[3])
        : "r"(a[0]), "r"(a[1]), "r"(a[2]), "r"(a[3]), "r"(b[0]), "r"(b[1]));
}

// ---- prep kernels (vectorized, one row per block, no div/mod) -------------
// Weights: [E][N][K] fp32 -> [E][Npad][K] tf32. grid = (Npad, E).
__global__ void cvt_rows(const float* __restrict__ src, float* __restrict__ dst,
                         int N, int K)
{
    const int row = blockIdx.x, e = blockIdx.y;
    const int Npad = gridDim.x;
    const int n4 = K >> 2;
    float4* d = (float4*)(dst + ((size_t)e * Npad + row) * K);
    if (row < N) {
        const float4* s = (const float4*)(src + ((size_t)e * N + row) * K);
        for (int i = threadIdx.x; i < n4; i += blockDim.x) d[i] = tfr4(s[i]);
    } else {
        const float4 zz = make_float4(0.f, 0.f, 0.f, 0.f);
        for (int i = threadIdx.x; i < n4; i += blockDim.x) d[i] = zz;
    }
}

// X = tf32(concat(motions, angles, z)); z tails into bufC/D/E. grid = 4096.
__global__ void pack_kernel(const float* __restrict__ motions,
                            const float* __restrict__ angles,
                            const float* __restrict__ z)
{
    const int b = blockIdx.x;
    float4* X = (float4*)(g_X + (size_t)b * 2368);
    const float4* m4 = (const float4*)(motions + (size_t)b * 1792);
    const float4* a4 = (const float4*)(angles + (size_t)b * 448);
    const float4* z4 = (const float4*)(z + (size_t)b * 128);
    for (int i = threadIdx.x; i < 592; i += blockDim.x) {
        float4 v = (i < 448) ? m4[i] : (i < 560) ? a4[i - 448] : z4[i - 560];
        X[i] = tfr4(v);
    }
    for (int i = threadIdx.x; i < 32; i += blockDim.x) {
        float4 v = tfr4(z4[i]);
        ((float4*)(g_bufC + (size_t)b * 2496 + 2368))[i] = v;
        ((float4*)(g_bufD + (size_t)b * 2176 + 2048))[i] = v;
        ((float4*)(g_bufE + (size_t)b * 2496 + 2368))[i] = v;
    }
}

// bufC[:, :2368] = tf32( sum_e E2[e] ).  grid = 4096 (one row per block).
__global__ void reduce_kernel()
{
    const int b = blockIdx.x;
    float4* dst = (float4*)(g_bufC + (size_t)b * 2496);
    for (int i = threadIdx.x; i < 592; i += blockDim.x) {
        float4 s = make_float4(0.f, 0.f, 0.f, 0.f);
        #pragma unroll
        for (int e = 0; e < 8; e++) {
            float4 v = ((const float4*)(g_E2 + ((size_t)e * BROWS + b) * 2368))[i];
            s.x += v.x; s.y += v.y; s.z += v.z; s.w += v.w;
        }
        dst[i] = tfr4(s);
    }
}

// ---- pipelined GEMM -------------------------------------------------------
// ROUND: tf32-round the output (feeds a later GEMM). PARA: scale by para[e].
template<bool ROUND, bool PARA>
__global__ void __launch_bounds__(256, 2)
gemm_pipe(const float* __restrict__ A0, int lda, size_t sAe,
          const float* __restrict__ W0, size_t sWe,
          const float* __restrict__ bias0, int sBe,
          const float* __restrict__ para,
          float* __restrict__ C0, int ldc, size_t sCe,
          int N, int K)
{
    extern __shared__ float smem[];
    const uint32_t sbase = smem_u32(smem);

    const int tid = threadIdx.x;
    const int lane = tid & 31, warp = tid >> 5;
    const int warpM = warp & 1, warpN = warp >> 1;       // 2 x 4 warps
    const int g = lane >> 2, tg = lane & 3;
    const int mBlock = blockIdx.y * BM;
    const int nBlock = blockIdx.x * BN;
    const int e = blockIdx.z;
    const int Kiters = K / BK;

    const float* A = A0 + (size_t)e * sAe;
    const float* W = W0 + (size_t)e * sWe;

    const int cr = tid >> 3;          // copy row base
    const int cc = (tid & 7) * 16;    // byte offset in 128B row chunk

    auto issue = [&](int stage, int kt) {
        uint32_t sa = sbase + stage * STG_BYTES;
        #pragma unroll
        for (int i = 0; i < 4; i++) {
            int r = cr + i * 32;
            cp16(sa + (uint32_t)(r * (LDSK * 4)) + cc,
                 A + (size_t)(mBlock + r) * lda + kt * BK + (cc >> 2));
        }
        uint32_t sw = sa + BM * LDSK * 4;
        #pragma unroll
        for (int i = 0; i < 4; i++) {
            int r = cr + i * 32;
            cp16(sw + (uint32_t)(r * (LDSK * 4)) + cc,
                 W + (size_t)(nBlock + r) * K + kt * BK + (cc >> 2));
        }
    };

    float acc[4][4][4];
    #pragma unroll
    for (int mi = 0; mi < 4; mi++)
        #pragma unroll
        for (int ni = 0; ni < 4; ni++)
            #pragma unroll
            for (int c = 0; c < 4; c++) acc[mi][ni][c] = 0.f;

    #pragma unroll
    for (int s = 0; s < STAGES - 1; s++) {
        if (s < Kiters) issue(s, s);
        cp_commit();
    }

    const uint32_t* Asm = (const uint32_t*)smem;
    for (int kt = 0; kt < Kiters; kt++) {
        cp_wait1();
        __syncthreads();

        int nxt = kt + STAGES - 1;
        if (nxt < Kiters) issue(nxt % STAGES, nxt);
        cp_commit();

        const int st = kt % STAGES;
        const uint32_t* Ab = Asm + st * STG_FLT + (warpM * 64) * LDSK;
        const uint32_t* Wb = Asm + st * STG_FLT + BM * LDSK + (warpN * 32) * LDSK;
        #pragma unroll
        for (int ks = 0; ks < 4; ks++) {
            uint32_t af[4][4], bf[4][2];
            const int kc = ks * 8 + tg;
            #pragma unroll
            for (int mi = 0; mi < 4; mi++) {
                const uint32_t* p = Ab + (mi * 16 + g) * LDSK + kc;
                af[mi][0] = p[0];
                af[mi][1] = p[8 * LDSK];
                af[mi][2] = p[4];
                af[mi][3] = p[8 * LDSK + 4];
            }
            #pragma unroll
            for (int ni = 0; ni < 4; ni++) {
                const uint32_t* p = Wb + (ni * 8 + g) * LDSK + kc;
                bf[ni][0] = p[0];
                bf[ni][1] = p[4];
            }
            #pragma unroll
            for (int mi = 0; mi < 4; mi++)
                #pragma unroll
                for (int ni = 0; ni < 4; ni++)
                    mma_tf32(acc[mi][ni], af[mi], bf[ni]);
        }
    }

    // epilogue: bias + ELU (+ para, + tf32 round), guarded store
    const float* bias = bias0 + (size_t)e * sBe;
    const float pe = PARA ? para[e] : 1.0f;
    float* C = C0 + (size_t)e * sCe;
    #pragma unroll
    for (int ni = 0; ni < 4; ni++) {
        int col0 = nBlock + warpN * 32 + ni * 8 + tg * 2;
        if (col0 >= N) continue;
        float b0 = bias[col0];
        float b1 = bias[col0 + 1];
        #pragma unroll
        for (int mi = 0; mi < 4; mi++) {
            int r0 = mBlock + warpM * 64 + mi * 16 + g;
            float y0 = elu1(acc[mi][ni][0] + b0) * pe;
            float y1 = elu1(acc[mi][ni][1] + b1) * pe;
            float y2 = elu1(acc[mi][ni][2] + b0) * pe;
            float y3 = elu1(acc[mi][ni][3] + b1) * pe;
            if (ROUND) { y0 = tfr(y0); y1 = tfr(y1); y2 = tfr(y2); y3 = tfr(y3); }
            *reinterpret_cast<float2*>(C + (size_t)r0 * ldc + col0) = make_float2(y0, y1);
            *reinterpret_cast<float2*>(C + (size_t)(r0 + 8) * ldc + col0) = make_float2(y2, y3);
        }
    }
}

// ---- launch ---------------------------------------------------------------
extern "C" void kernel_launch(void* const* d_in, const int* in_sizes, int n_in,
                              void* d_out, int out_size)
{
    const float* motions = (const float*)d_in[0];
    const float* angles  = (const float*)d_in[1];
    const float* z       = (const float*)d_in[2];
    const float* l1_w    = (const float*)d_in[3];
    const float* l1_b    = (const float*)d_in[4];
    const float* l2_w    = (const float*)d_in[5];
    const float* l2_b    = (const float*)d_in[6];
    const float* para    = (const float*)d_in[7];
    const float* l3_w    = (const float*)d_in[8];
    const float* l3_b    = (const float*)d_in[9];
    const float* l4_w    = (const float*)d_in[10];
    const float* l4_b    = (const float*)d_in[11];
    const float* l5_w    = (const float*)d_in[12];
    const float* l5_b    = (const float*)d_in[13];
    float* out = (float*)d_out;

    float *X, *H1, *W1c, *W2c, *W3c, *W4c, *W5c, *bufC, *bufD, *bufE;
    cudaGetSymbolAddress((void**)&X,    g_X);
    cudaGetSymbolAddress((void**)&H1,   g_H1);
    cudaGetSymbolAddress((void**)&W1c,  g_W1c);
    cudaGetSymbolAddress((void**)&W2c,  g_W2c);
    cudaGetSymbolAddress((void**)&W3c,  g_W3c);
    cudaGetSymbolAddress((void**)&W4c,  g_W4c);
    cudaGetSymbolAddress((void**)&W5c,  g_W5c);
    cudaGetSymbolAddress((void**)&bufC, g_bufC);
    cudaGetSymbolAddress((void**)&bufD, g_bufD);
    cudaGetSymbolAddress((void**)&bufE, g_bufE);
    float* E2; cudaGetSymbolAddress((void**)&E2, g_E2);

    const int SH = STAGES * STG_BYTES;   // 110592 B
    cudaFuncSetAttribute(gemm_pipe<true,  false>, cudaFuncAttributeMaxDynamicSharedMemorySize, SH);
    cudaFuncSetAttribute(gemm_pipe<false, true >, cudaFuncAttributeMaxDynamicSharedMemorySize, SH);
    cudaFuncSetAttribute(gemm_pipe<false, false>, cudaFuncAttributeMaxDynamicSharedMemorySize, SH);

    // prep: inputs + weights -> tf32 (vectorized; weights N-padded where needed)
    pack_kernel<<<4096, 256>>>(motions, angles, z);
    cvt_rows<<<dim3(2048, 8), 256>>>(l1_w, W1c, 2048, 2368);
    cvt_rows<<<dim3(2432, 8), 256>>>(l2_w, W2c, 2368, 2048);
    cvt_rows<<<dim3(2048, 1), 256>>>(l3_w, W3c, 2048, 2496);
    cvt_rows<<<dim3(2432, 1), 256>>>(l4_w, W4c, 2368, 2176);
    cvt_rows<<<dim3( 256, 1), 256>>>(l5_w, W5c,  256, 2496);

    // L1: H1[e] = tf32(elu(X @ W1[e]^T + b1[e]))   K=2368
    gemm_pipe<true, false><<<dim3(16, 32, 8), 256, SH>>>(
        X, 2368, (size_t)0,
        W1c, (size_t)2048 * 2368,
        l1_b, 2048, nullptr,
        H1, 2048, (size_t)BROWS * 2048,
        2048, 2368);

    // L2: E2[e] = para[e] * elu(H1[e] @ W2[e]^T + b2[e])   K=2048, N=2368(pad 2432)
    gemm_pipe<false, true><<<dim3(19, 32, 8), 256, SH>>>(
        H1, 2048, (size_t)BROWS * 2048,
        W2c, (size_t)2432 * 2048,
        l2_b, 2368, para,
        E2, 2368, (size_t)BROWS * 2368,
        2368, 2048);

    // expert sum -> bufC[:, :2368] (tf32)
    reduce_kernel<<<4096, 256>>>();

    // L3: bufD = tf32(elu(bufC @ W3^T + b3))   K=2496
    gemm_pipe<true, false><<<dim3(16, 32, 1), 256, SH>>>(
        bufC, 2496, (size_t)0, W3c, (size_t)0, l3_b, 0, nullptr,
        bufD, 2176, (size_t)0, 2048, 2496);

    // L4: bufE = tf32(elu(bufD @ W4^T + b4))   K=2176, N=2368(pad 2432)
    gemm_pipe<true, false><<<dim3(19, 32, 1), 256, SH>>>(
        bufD, 2176, (size_t)0, W4c, (size_t)0, l4_b, 0, nullptr,
        bufE, 2496, (size_t)0, 2368, 2176);

    // L5: out = elu(bufE @ W5^T + b5)   K=2496, N=256
    gemm_pipe<false, false><<<dim3(2, 32, 1), 256, SH>>>(
        bufE, 2496, (size_t)0, W5c, (size_t)0, l5_b, 0, nullptr,
        out, 256, (size_t)0, 256, 2496);
}

// round 14
// speedup vs baseline: 1.9290x; 1.7015x over previous
#include <cuda_runtime.h>
#include <cstdint>

// ===========================================================================
// VAE decoder, sm_103 fallback tensor path (mma.sync m16n8k8 tf32).
// All operands pre-rounded to tf32 in GMEM (vectorized cvt); GEMM mainloop is
// a 3-stage cp.async pipeline, 2 CTAs/SM, with ldmatrix.x4 fragment loads
// (24 LDSM vs 96 LDS.32 per warp-ktile). L2 expert sum via per-expert planes
// + separate vectorized reduce (in-register fold spills - measured r10).
// GEMMs: A[M,K] row * W[N,K] row^T -> C[M,N], M=4096, K%32==0.
// ===========================================================================

#define BROWS 4096
#define BM 128
#define BN 128
#define BK 32
#define LDSK 36            // pad: bank = (4r+c)%32 -> conflict-free frags/LDSM
#define STAGES 3
#define STG_FLT (2 * BM * LDSK)        // floats per stage (A + W) = 9216
#define STG_BYTES (STG_FLT * 4)        // 36864

// ---- scratch (device globals; allocation-free) ----------------------------
__device__ float g_X  [(size_t)BROWS * 2368];            // tf32
__device__ float g_H1 [(size_t)8 * BROWS * 2048];        // tf32
__device__ float g_W1c[(size_t)8 * 2048 * 2368];         // tf32
__device__ float g_W2c[(size_t)8 * 2432 * 2048];         // tf32, N padded
__device__ float g_W3c[(size_t)2048 * 2496];
__device__ float g_W4c[(size_t)2432 * 2176];             // N padded
__device__ float g_W5c[(size_t)256 * 2496];
__device__ float g_bufC[(size_t)BROWS * 2496];           // L2 sum + z tail
__device__ float g_bufD[(size_t)BROWS * 2176];           // L3 out + z tail
__device__ float g_bufE[(size_t)BROWS * 2496];           // L4 out + z tail
__device__ float g_E2 [(size_t)8 * BROWS * 2368];        // per-expert L2 (fp32)

// ---- helpers --------------------------------------------------------------
__device__ __forceinline__ uint32_t f2tf(float x) {
    uint32_t r; asm("cvt.rna.tf32.f32 %0, %1;" : "=r"(r) : "f"(x)); return r;
}
__device__ __forceinline__ float tfr(float x) { return __uint_as_float(f2tf(x)); }
__device__ __forceinline__ float4 tfr4(float4 v) {
    return make_float4(tfr(v.x), tfr(v.y), tfr(v.z), tfr(v.w));
}
__device__ __forceinline__ float elu1(float x) { return x > 0.f ? x : expm1f(x); }
__device__ __forceinline__ uint32_t smem_u32(const void* p) {
    uint32_t a;
    asm("{ .reg .u64 t; cvta.to.shared.u64 t, %1; cvt.u32.u64 %0, t; }" : "=r"(a) : "l"(p));
    return a;
}
__device__ __forceinline__ void cp16(uint32_t d, const void* s) {
    asm volatile("cp.async.cg.shared.global [%0], [%1], 16;" :: "r"(d), "l"(s) : "memory");
}
__device__ __forceinline__ void cp_commit() {
    asm volatile("cp.async.commit_group;" ::: "memory");
}
__device__ __forceinline__ void cp_wait1() {
    asm volatile("cp.async.wait_group 1;" ::: "memory");
}
__device__ __forceinline__ void ldsm4(uint32_t r[4], uint32_t addr) {
    asm volatile("ldmatrix.sync.aligned.m8n8.x4.shared.b16 {%0,%1,%2,%3}, [%4];"
        : "=r"(r[0]), "=r"(r[1]), "=r"(r[2]), "=r"(r[3]) : "r"(addr));
}
__device__ __forceinline__ void mma_tf32(float c[4], const uint32_t a[4], const uint32_t b[2]) {
    asm volatile(
        "mma.sync.aligned.m16n8k8.row.col.f32.tf32.tf32.f32 "
        "{%0,%1,%2,%3}, {%4,%5,%6,%7}, {%8,%9}, {%0,%1,%2,%3};\n"
        : "+f"(c[0]), "+f"(c[1]), "+f"(c[2]), "+f"(c[3])
        : "r"(a[0]), "r"(a[1]), "r"(a[2]), "r"(a[3]), "r"(b[0]), "r"(b[1]));
}

// ---- prep kernels (vectorized, one row per block, no div/mod) -------------
// Weights: [E][N][K] fp32 -> [E][Npad][K] tf32. grid = (Npad, E).
__global__ void cvt_rows(const float* __restrict__ src, float* __restrict__ dst,
                         int N, int K)
{
    const int row = blockIdx.x, e = blockIdx.y;
    const int Npad = gridDim.x;
    const int n4 = K >> 2;
    float4* d = (float4*)(dst + ((size_t)e * Npad + row) * K);
    if (row < N) {
        const float4* s = (const float4*)(src + ((size_t)e * N + row) * K);
        for (int i = threadIdx.x; i < n4; i += blockDim.x) d[i] = tfr4(s[i]);
    } else {
        const float4 zz = make_float4(0.f, 0.f, 0.f, 0.f);
        for (int i = threadIdx.x; i < n4; i += blockDim.x) d[i] = zz;
    }
}

// X = tf32(concat(motions, angles, z)); z tails into bufC/D/E. grid = 4096.
__global__ void pack_kernel(const float* __restrict__ motions,
                            const float* __restrict__ angles,
                            const float* __restrict__ z)
{
    const int b = blockIdx.x;
    float4* X = (float4*)(g_X + (size_t)b * 2368);
    const float4* m4 = (const float4*)(motions + (size_t)b * 1792);
    const float4* a4 = (const float4*)(angles + (size_t)b * 448);
    const float4* z4 = (const float4*)(z + (size_t)b * 128);
    for (int i = threadIdx.x; i < 592; i += blockDim.x) {
        float4 v = (i < 448) ? m4[i] : (i < 560) ? a4[i - 448] : z4[i - 560];
        X[i] = tfr4(v);
    }
    for (int i = threadIdx.x; i < 32; i += blockDim.x) {
        float4 v = tfr4(z4[i]);
        ((float4*)(g_bufC + (size_t)b * 2496 + 2368))[i] = v;
        ((float4*)(g_bufD + (size_t)b * 2176 + 2048))[i] = v;
        ((float4*)(g_bufE + (size_t)b * 2496 + 2368))[i] = v;
    }
}

// bufC[:, :2368] = tf32( sum_e E2[e] ).  grid = 4096 (one row per block).
__global__ void reduce_kernel()
{
    const int b = blockIdx.x;
    float4* dst = (float4*)(g_bufC + (size_t)b * 2496);
    for (int i = threadIdx.x; i < 592; i += blockDim.x) {
        float4 s = make_float4(0.f, 0.f, 0.f, 0.f);
        #pragma unroll
        for (int e = 0; e < 8; e++) {
            float4 v = ((const float4*)(g_E2 + ((size_t)e * BROWS + b) * 2368))[i];
            s.x += v.x; s.y += v.y; s.z += v.z; s.w += v.w;
        }
        dst[i] = tfr4(s);
    }
}

// ---- pipelined GEMM -------------------------------------------------------
// ROUND: tf32-round the output (feeds a later GEMM). PARA: scale by para[e].
template<bool ROUND, bool PARA>
__global__ void __launch_bounds__(256, 2)
gemm_pipe(const float* __restrict__ A0, int lda, size_t sAe,
          const float* __restrict__ W0, size_t sWe,
          const float* __restrict__ bias0, int sBe,
          const float* __restrict__ para,
          float* __restrict__ C0, int ldc, size_t sCe,
          int N, int K)
{
    extern __shared__ float smem[];
    const uint32_t sbase = smem_u32(smem);

    const int tid = threadIdx.x;
    const int lane = tid & 31, warp = tid >> 5;
    const int warpM = warp & 1, warpN = warp >> 1;       // 2 x 4 warps
    const int g = lane >> 2, tg = lane & 3;
    const int mBlock = blockIdx.y * BM;
    const int nBlock = blockIdx.x * BN;
    const int e = blockIdx.z;
    const int Kiters = K / BK;

    const float* A = A0 + (size_t)e * sAe;
    const float* W = W0 + (size_t)e * sWe;

    const int cr = tid >> 3;          // copy row base
    const int cc = (tid & 7) * 16;    // byte offset in 128B row chunk

    // ldmatrix per-lane offsets (bytes):
    //   A frags: M0/M1 = row octets (+0,+8) at k-half 0; M2/M3 = same at k-half 1
    //   B frags: M0/M1 = k-half 0/1 of row octet +0; M2/M3 = k-half 0/1 of +8
    const int r8 = lane & 7, sel = lane >> 3;
    const uint32_t aoff = (uint32_t)((((sel & 1) * 8 + r8) * LDSK + (sel >> 1) * 4) * 4);
    const uint32_t boff = (uint32_t)((((sel >> 1) * 8 + r8) * LDSK + (sel & 1) * 4) * 4);

    auto issue = [&](int stage, int kt) {
        uint32_t sa = sbase + stage * STG_BYTES;
        #pragma unroll
        for (int i = 0; i < 4; i++) {
            int r = cr + i * 32;
            cp16(sa + (uint32_t)(r * (LDSK * 4)) + cc,
                 A + (size_t)(mBlock + r) * lda + kt * BK + (cc >> 2));
        }
        uint32_t sw = sa + BM * LDSK * 4;
        #pragma unroll
        for (int i = 0; i < 4; i++) {
            int r = cr + i * 32;
            cp16(sw + (uint32_t)(r * (LDSK * 4)) + cc,
                 W + (size_t)(nBlock + r) * K + kt * BK + (cc >> 2));
        }
    };

    float acc[4][4][4];
    #pragma unroll
    for (int mi = 0; mi < 4; mi++)
        #pragma unroll
        for (int ni = 0; ni < 4; ni++)
            #pragma unroll
            for (int c = 0; c < 4; c++) acc[mi][ni][c] = 0.f;

    #pragma unroll
    for (int s = 0; s < STAGES - 1; s++) {
        if (s < Kiters) issue(s, s);
        cp_commit();
    }

    for (int kt = 0; kt < Kiters; kt++) {
        cp_wait1();
        __syncthreads();

        int nxt = kt + STAGES - 1;
        if (nxt < Kiters) issue(nxt % STAGES, nxt);
        cp_commit();

        const int st = kt % STAGES;
        const uint32_t Ab = sbase + st * STG_BYTES
                          + (uint32_t)(warpM * 64 * LDSK * 4) + aoff;
        const uint32_t Wb = sbase + st * STG_BYTES + (uint32_t)(BM * LDSK * 4)
                          + (uint32_t)(warpN * 32 * LDSK * 4) + boff;
        #pragma unroll
        for (int ks = 0; ks < 4; ks++) {
            uint32_t a[4][4], b[2][4];
            #pragma unroll
            for (int mi = 0; mi < 4; mi++)
                ldsm4(a[mi], Ab + (uint32_t)(mi * 16 * LDSK * 4) + ks * 32);
            #pragma unroll
            for (int p = 0; p < 2; p++)
                ldsm4(b[p], Wb + (uint32_t)(p * 16 * LDSK * 4) + ks * 32);
            #pragma unroll
            for (int mi = 0; mi < 4; mi++)
                #pragma unroll
                for (int ni = 0; ni < 4; ni++)
                    mma_tf32(acc[mi][ni], a[mi], &b[ni >> 1][(ni & 1) * 2]);
        }
    }

    // epilogue: bias + ELU (+ para, + tf32 round), guarded store
    const float* bias = bias0 + (size_t)e * sBe;
    const float pe = PARA ? para[e] : 1.0f;
    float* C = C0 + (size_t)e * sCe;
    #pragma unroll
    for (int ni = 0; ni < 4; ni++) {
        int col0 = nBlock + warpN * 32 + ni * 8 + tg * 2;
        if (col0 >= N) continue;
        float b0 = bias[col0];
        float b1 = bias[col0 + 1];
        #pragma unroll
        for (int mi = 0; mi < 4; mi++) {
            int r0 = mBlock + warpM * 64 + mi * 16 + g;
            float y0 = elu1(acc[mi][ni][0] + b0) * pe;
            float y1 = elu1(acc[mi][ni][1] + b1) * pe;
            float y2 = elu1(acc[mi][ni][2] + b0) * pe;
            float y3 = elu1(acc[mi][ni][3] + b1) * pe;
            if (ROUND) { y0 = tfr(y0); y1 = tfr(y1); y2 = tfr(y2); y3 = tfr(y3); }
            *reinterpret_cast<float2*>(C + (size_t)r0 * ldc + col0) = make_float2(y0, y1);
            *reinterpret_cast<float2*>(C + (size_t)(r0 + 8) * ldc + col0) = make_float2(y2, y3);
        }
    }
}

// ---- launch ---------------------------------------------------------------
extern "C" void kernel_launch(void* const* d_in, const int* in_sizes, int n_in,
                              void* d_out, int out_size)
{
    const float* motions = (const float*)d_in[0];
    const float* angles  = (const float*)d_in[1];
    const float* z       = (const float*)d_in[2];
    const float* l1_w    = (const float*)d_in[3];
    const float* l1_b    = (const float*)d_in[4];
    const float* l2_w    = (const float*)d_in[5];
    const float* l2_b    = (const float*)d_in[6];
    const float* para    = (const float*)d_in[7];
    const float* l3_w    = (const float*)d_in[8];
    const float* l3_b    = (const float*)d_in[9];
    const float* l4_w    = (const float*)d_in[10];
    const float* l4_b    = (const float*)d_in[11];
    const float* l5_w    = (const float*)d_in[12];
    const float* l5_b    = (const float*)d_in[13];
    float* out = (float*)d_out;

    float *X, *H1, *W1c, *W2c, *W3c, *W4c, *W5c, *bufC, *bufD, *bufE, *E2;
    cudaGetSymbolAddress((void**)&X,    g_X);
    cudaGetSymbolAddress((void**)&H1,   g_H1);
    cudaGetSymbolAddress((void**)&W1c,  g_W1c);
    cudaGetSymbolAddress((void**)&W2c,  g_W2c);
    cudaGetSymbolAddress((void**)&W3c,  g_W3c);
    cudaGetSymbolAddress((void**)&W4c,  g_W4c);
    cudaGetSymbolAddress((void**)&W5c,  g_W5c);
    cudaGetSymbolAddress((void**)&bufC, g_bufC);
    cudaGetSymbolAddress((void**)&bufD, g_bufD);
    cudaGetSymbolAddress((void**)&bufE, g_bufE);
    cudaGetSymbolAddress((void**)&E2,   g_E2);

    const int SH = STAGES * STG_BYTES;   // 110592 B
    cudaFuncSetAttribute(gemm_pipe<true,  false>, cudaFuncAttributeMaxDynamicSharedMemorySize, SH);
    cudaFuncSetAttribute(gemm_pipe<false, true >, cudaFuncAttributeMaxDynamicSharedMemorySize, SH);
    cudaFuncSetAttribute(gemm_pipe<false, false>, cudaFuncAttributeMaxDynamicSharedMemorySize, SH);

    // prep: inputs + weights -> tf32 (vectorized; weights N-padded where needed)
    pack_kernel<<<4096, 256>>>(motions, angles, z);
    cvt_rows<<<dim3(2048, 8), 256>>>(l1_w, W1c, 2048, 2368);
    cvt_rows<<<dim3(2432, 8), 256>>>(l2_w, W2c, 2368, 2048);
    cvt_rows<<<dim3(2048, 1), 256>>>(l3_w, W3c, 2048, 2496);
    cvt_rows<<<dim3(2432, 1), 256>>>(l4_w, W4c, 2368, 2176);
    cvt_rows<<<dim3( 256, 1), 256>>>(l5_w, W5c,  256, 2496);

    // L1: H1[e] = tf32(elu(X @ W1[e]^T + b1[e]))   K=2368
    gemm_pipe<true, false><<<dim3(16, 32, 8), 256, SH>>>(
        X, 2368, (size_t)0,
        W1c, (size_t)2048 * 2368,
        l1_b, 2048, nullptr,
        H1, 2048, (size_t)BROWS * 2048,
        2048, 2368);

    // L2: E2[e] = para[e] * elu(H1[e] @ W2[e]^T + b2[e])   K=2048, N=2368(pad 2432)
    gemm_pipe<false, true><<<dim3(19, 32, 8), 256, SH>>>(
        H1, 2048, (size_t)BROWS * 2048,
        W2c, (size_t)2432 * 2048,
        l2_b, 2368, para,
        E2, 2368, (size_t)BROWS * 2368,
        2368, 2048);

    // expert sum -> bufC[:, :2368] (tf32)
    reduce_kernel<<<4096, 256>>>();

    // L3: bufD = tf32(elu(bufC @ W3^T + b3))   K=2496
    gemm_pipe<true, false><<<dim3(16, 32, 1), 256, SH>>>(
        bufC, 2496, (size_t)0, W3c, (size_t)0, l3_b, 0, nullptr,
        bufD, 2176, (size_t)0, 2048, 2496);

    // L4: bufE = tf32(elu(bufD @ W4^T + b4))   K=2176, N=2368(pad 2432)
    gemm_pipe<true, false><<<dim3(19, 32, 1), 256, SH>>>(
        bufD, 2176, (size_t)0, W4c, (size_t)0, l4_b, 0, nullptr,
        bufE, 2496, (size_t)0, 2368, 2176);

    // L5: out = elu(bufE @ W5^T + b5)   K=2496, N=256
    gemm_pipe<false, false><<<dim3(2, 32, 1), 256, SH>>>(
        bufE, 2496, (size_t)0, W5c, (size_t)0, l5_b, 0, nullptr,
        out, 256, (size_t)0, 256, 2496);
}

// round 16
// speedup vs baseline: 2.8133x; 1.4584x over previous
#include <cuda_runtime.h>
#include <cuda_fp16.h>
#include <cstdint>

// ===========================================================================
// VAE decoder, sm_103 fallback tensor path, fp16 mma.sync m16n8k16 (fp32 acc).
// fp16 mantissa == tf32 mantissa (10 bits), so numerics match the proven tf32
// path; k16 doubles FLOP/instr and halves operand traffic.
// 4-stage cp.async pipeline, 2 CTAs/SM, ldmatrix.x4 fragment loads.
// L2 expert sum via fp32 per-expert planes + vectorized reduce.
// GEMMs: A[M,K] row * W[N,K] row^T -> C[M,N], M=4096, K%32==0.
// ===========================================================================

#define BROWS 4096
#define BM 128
#define BN 128
#define BK 32
#define LDSKH 40                         // halfs/row: 80B, conflict-free LDSM
#define STAGES 4
#define OP_BYTES (128 * LDSKH * 2)       // one operand per stage = 10240 B
#define STG_BYTES (2 * OP_BYTES)         // 20480 B

// ---- scratch (device globals; allocation-free) ----------------------------
__device__ __align__(128) __half g_X  [(size_t)BROWS * 2368];
__device__ __align__(128) __half g_H1 [(size_t)8 * BROWS * 2048];
__device__ __align__(128) __half g_W1h[(size_t)8 * 2048 * 2368];
__device__ __align__(128) __half g_W2h[(size_t)8 * 2432 * 2048];   // N padded
__device__ __align__(128) __half g_W3h[(size_t)2048 * 2496];
__device__ __align__(128) __half g_W4h[(size_t)2432 * 2176];       // N padded
__device__ __align__(128) __half g_W5h[(size_t)256 * 2496];
__device__ __align__(128) __half g_bufC[(size_t)BROWS * 2496];     // L2 sum + z
__device__ __align__(128) __half g_bufD[(size_t)BROWS * 2176];     // L3 out + z
__device__ __align__(128) __half g_bufE[(size_t)BROWS * 2496];     // L4 out + z
__device__ __align__(128) float  g_E2 [(size_t)8 * BROWS * 2368];  // fp32 planes

// ---- helpers --------------------------------------------------------------
__device__ __forceinline__ float elu1(float x) { return x > 0.f ? x : expm1f(x); }
__device__ __forceinline__ uint32_t smem_u32(const void* p) {
    uint32_t a;
    asm("{ .reg .u64 t; cvta.to.shared.u64 t, %1; cvt.u32.u64 %0, t; }" : "=r"(a) : "l"(p));
    return a;
}
__device__ __forceinline__ void cp16(uint32_t d, const void* s) {
    asm volatile("cp.async.cg.shared.global [%0], [%1], 16;" :: "r"(d), "l"(s) : "memory");
}
__device__ __forceinline__ void cp_commit() {
    asm volatile("cp.async.commit_group;" ::: "memory");
}
__device__ __forceinline__ void cp_wait2() {
    asm volatile("cp.async.wait_group 2;" ::: "memory");
}
__device__ __forceinline__ void ldsm4(uint32_t r[4], uint32_t addr) {
    asm volatile("ldmatrix.sync.aligned.m8n8.x4.shared.b16 {%0,%1,%2,%3}, [%4];"
        : "=r"(r[0]), "=r"(r[1]), "=r"(r[2]), "=r"(r[3]) : "r"(addr));
}
__device__ __forceinline__ void mma_fp16(float c[4], const uint32_t a[4],
                                         uint32_t b0, uint32_t b1) {
    asm volatile(
        "mma.sync.aligned.m16n8k16.row.col.f32.f16.f16.f32 "
        "{%0,%1,%2,%3}, {%4,%5,%6,%7}, {%8,%9}, {%0,%1,%2,%3};\n"
        : "+f"(c[0]), "+f"(c[1]), "+f"(c[2]), "+f"(c[3])
        : "r"(a[0]), "r"(a[1]), "r"(a[2]), "r"(a[3]), "r"(b0), "r"(b1));
}
// 4 floats -> 4 halfs (8B)
__device__ __forceinline__ void store4h(__half* p, float4 v) {
    half2 h0 = __floats2half2_rn(v.x, v.y);
    half2 h1 = __floats2half2_rn(v.z, v.w);
    uint2 u;
    u.x = *(uint32_t*)&h0; u.y = *(uint32_t*)&h1;
    *(uint2*)p = u;
}
__device__ __forceinline__ void store2(float* p, float a, float b) {
    *(float2*)p = make_float2(a, b);
}
__device__ __forceinline__ void store2(__half* p, float a, float b) {
    *(half2*)p = __floats2half2_rn(a, b);
}

// ---- prep kernels ---------------------------------------------------------
// Weights: [E][N][K] fp32 -> [E][Npad][K] fp16. grid = (Npad, E).
__global__ void cvt_rows(const float* __restrict__ src, __half* __restrict__ dst,
                         int N, int K)
{
    const int row = blockIdx.x, e = blockIdx.y;
    const int Npad = gridDim.x;
    const int n4 = K >> 2;
    __half* d = dst + ((size_t)e * Npad + row) * K;
    if (row < N) {
        const float4* s = (const float4*)(src + ((size_t)e * N + row) * K);
        for (int i = threadIdx.x; i < n4; i += blockDim.x) store4h(d + 4*i, s[i]);
    } else {
        const float4 zz = make_float4(0.f, 0.f, 0.f, 0.f);
        for (int i = threadIdx.x; i < n4; i += blockDim.x) store4h(d + 4*i, zz);
    }
}

// X = fp16(concat(motions, angles, z)); z tails into bufC/D/E; W5 cvt folded in.
__global__ void pack_kernel(const float* __restrict__ motions,
                            const float* __restrict__ angles,
                            const float* __restrict__ z,
                            const float* __restrict__ l5_w)
{
    const int b = blockIdx.x;
    __half* X = g_X + (size_t)b * 2368;
    const float4* m4 = (const float4*)(motions + (size_t)b * 1792);
    const float4* a4 = (const float4*)(angles + (size_t)b * 448);
    const float4* z4 = (const float4*)(z + (size_t)b * 128);
    for (int i = threadIdx.x; i < 592; i += blockDim.x) {
        float4 v = (i < 448) ? m4[i] : (i < 560) ? a4[i - 448] : z4[i - 560];
        store4h(X + 4*i, v);
    }
    for (int i = threadIdx.x; i < 32; i += blockDim.x) {
        float4 v = z4[i];
        store4h(g_bufC + (size_t)b * 2496 + 2368 + 4*i, v);
        store4h(g_bufD + (size_t)b * 2176 + 2048 + 4*i, v);
        store4h(g_bufE + (size_t)b * 2496 + 2368 + 4*i, v);
    }
    if (b < 256) {   // W5 row b
        const float4* s = (const float4*)(l5_w + (size_t)b * 2496);
        __half* d = g_W5h + (size_t)b * 2496;
        for (int i = threadIdx.x; i < 624; i += blockDim.x) store4h(d + 4*i, s[i]);
    }
}

// bufC[:, :2368] = fp16( sum_e E2[e] ).  grid = 4096.
__global__ void reduce_kernel()
{
    const int b = blockIdx.x;
    __half* dst = g_bufC + (size_t)b * 2496;
    for (int i = threadIdx.x; i < 592; i += blockDim.x) {
        float4 s = make_float4(0.f, 0.f, 0.f, 0.f);
        #pragma unroll
        for (int e = 0; e < 8; e++) {
            float4 v = ((const float4*)(g_E2 + ((size_t)e * BROWS + b) * 2368))[i];
            s.x += v.x; s.y += v.y; s.z += v.z; s.w += v.w;
        }
        store4h(dst + 4*i, s);
    }
}

// ---- pipelined fp16 GEMM --------------------------------------------------
// OutT=__half: next-GEMM input (rounds to fp16). OutT=float: plain fp32 out.
template<bool PARA, typename OutT>
__global__ void __launch_bounds__(256, 2)
gemm_pipe(const __half* __restrict__ A0, int lda, size_t sAe,
          const __half* __restrict__ W0, size_t sWe,
          const float* __restrict__ bias0, int sBe,
          const float* __restrict__ para,
          OutT* __restrict__ C0, int ldc, size_t sCe,
          int N, int K)
{
    extern __shared__ __half smem[];
    const uint32_t sbase = smem_u32(smem);

    const int tid = threadIdx.x;
    const int lane = tid & 31, warp = tid >> 5;
    const int warpM = warp & 1, warpN = warp >> 1;       // 2 x 4 warps
    const int g = lane >> 2, tg = lane & 3;
    const int mBlock = blockIdx.y * BM;
    const int nBlock = blockIdx.x * BN;
    const int e = blockIdx.z;
    const int Kiters = K / BK;

    const __half* A = A0 + (size_t)e * sAe;
    const __half* W = W0 + (size_t)e * sWe;

    const int cr = tid >> 2;          // copy row base (0..63)
    const int ccB = (tid & 3) * 16;   // byte offset within 64B row
    const int ch = (tid & 3) * 8;     // half offset

    // ldmatrix per-lane offset (bytes), same for A and B tiles:
    // lanes 0-7: rows 0-7 khalf0 | 8-15: rows 8-15 khalf0
    // lanes 16-23: rows 0-7 khalf1 | 24-31: rows 8-15 khalf1
    const int r8 = lane & 7, sel = lane >> 3;
    const uint32_t frag_off =
        (uint32_t)((((sel & 1) * 8 + r8) * LDSKH + (sel >> 1) * 8) * 2);

    auto issue = [&](int stage, int kt) {
        uint32_t sa = sbase + stage * STG_BYTES;
        #pragma unroll
        for (int i = 0; i < 2; i++) {
            int r = cr + i * 64;
            cp16(sa + (uint32_t)(r * (LDSKH * 2)) + ccB,
                 A + (size_t)(mBlock + r) * lda + kt * BK + ch);
        }
        uint32_t sw = sa + OP_BYTES;
        #pragma unroll
        for (int i = 0; i < 2; i++) {
            int r = cr + i * 64;
            cp16(sw + (uint32_t)(r * (LDSKH * 2)) + ccB,
                 W + (size_t)(nBlock + r) * K + kt * BK + ch);
        }
    };

    float acc[4][4][4];
    #pragma unroll
    for (int mi = 0; mi < 4; mi++)
        #pragma unroll
        for (int ni = 0; ni < 4; ni++)
            #pragma unroll
            for (int c = 0; c < 4; c++) acc[mi][ni][c] = 0.f;

    #pragma unroll
    for (int s = 0; s < STAGES - 1; s++) {
        if (s < Kiters) issue(s, s);
        cp_commit();
    }

    for (int kt = 0; kt < Kiters; kt++) {
        cp_wait2();
        __syncthreads();

        int nxt = kt + STAGES - 1;
        if (nxt < Kiters) issue(nxt % STAGES, nxt);
        cp_commit();

        const int st = kt % STAGES;
        const uint32_t Ab = sbase + st * STG_BYTES
                          + (uint32_t)(warpM * 64 * LDSKH * 2) + frag_off;
        const uint32_t Wb = sbase + st * STG_BYTES + OP_BYTES
                          + (uint32_t)(warpN * 32 * LDSKH * 2) + frag_off;
        #pragma unroll
        for (int ks = 0; ks < 2; ks++) {       // two k16 steps per BK=32
            uint32_t a[4][4], b[2][4];
            #pragma unroll
            for (int mi = 0; mi < 4; mi++)
                ldsm4(a[mi], Ab + (uint32_t)(mi * 16 * LDSKH * 2) + ks * 32);
            #pragma unroll
            for (int p = 0; p < 2; p++)
                ldsm4(b[p], Wb + (uint32_t)(p * 16 * LDSKH * 2) + ks * 32);
            // b[p]: r0=n(0-7)k0-7, r1=n(8-15)k0-7, r2=n(0-7)k8-15, r3=n(8-15)k8-15
            #pragma unroll
            for (int mi = 0; mi < 4; mi++)
                #pragma unroll
                for (int ni = 0; ni < 4; ni++)
                    mma_fp16(acc[mi][ni], a[mi],
                             b[ni >> 1][ni & 1], b[ni >> 1][(ni & 1) + 2]);
        }
    }

    // epilogue: bias + ELU (+ para), store (fp16 round via OutT=__half)
    const float* bias = bias0 + (size_t)e * sBe;
    const float pe = PARA ? para[e] : 1.0f;
    OutT* C = C0 + (size_t)e * sCe;
    #pragma unroll
    for (int ni = 0; ni < 4; ni++) {
        int col0 = nBlock + warpN * 32 + ni * 8 + tg * 2;
        if (col0 >= N) continue;
        float b0 = bias[col0];
        float b1 = bias[col0 + 1];
        #pragma unroll
        for (int mi = 0; mi < 4; mi++) {
            int r0 = mBlock + warpM * 64 + mi * 16 + g;
            store2(C + (size_t)r0 * ldc + col0,
                   elu1(acc[mi][ni][0] + b0) * pe, elu1(acc[mi][ni][1] + b1) * pe);
            store2(C + (size_t)(r0 + 8) * ldc + col0,
                   elu1(acc[mi][ni][2] + b0) * pe, elu1(acc[mi][ni][3] + b1) * pe);
        }
    }
}

// ---- launch ---------------------------------------------------------------
extern "C" void kernel_launch(void* const* d_in, const int* in_sizes, int n_in,
                              void* d_out, int out_size)
{
    const float* motions = (const float*)d_in[0];
    const float* angles  = (const float*)d_in[1];
    const float* z       = (const float*)d_in[2];
    const float* l1_w    = (const float*)d_in[3];
    const float* l1_b    = (const float*)d_in[4];
    const float* l2_w    = (const float*)d_in[5];
    const float* l2_b    = (const float*)d_in[6];
    const float* para    = (const float*)d_in[7];
    const float* l3_w    = (const float*)d_in[8];
    const float* l3_b    = (const float*)d_in[9];
    const float* l4_w    = (const float*)d_in[10];
    const float* l4_b    = (const float*)d_in[11];
    const float* l5_w    = (const float*)d_in[12];
    const float* l5_b    = (const float*)d_in[13];
    float* out = (float*)d_out;

    __half *X, *H1, *W1h, *W2h, *W3h, *W4h, *W5h, *bufC, *bufD, *bufE;
    float* E2;
    cudaGetSymbolAddress((void**)&X,    g_X);
    cudaGetSymbolAddress((void**)&H1,   g_H1);
    cudaGetSymbolAddress((void**)&W1h,  g_W1h);
    cudaGetSymbolAddress((void**)&W2h,  g_W2h);
    cudaGetSymbolAddress((void**)&W3h,  g_W3h);
    cudaGetSymbolAddress((void**)&W4h,  g_W4h);
    cudaGetSymbolAddress((void**)&W5h,  g_W5h);
    cudaGetSymbolAddress((void**)&bufC, g_bufC);
    cudaGetSymbolAddress((void**)&bufD, g_bufD);
    cudaGetSymbolAddress((void**)&bufE, g_bufE);
    cudaGetSymbolAddress((void**)&E2,   g_E2);

    const int SH = STAGES * STG_BYTES;   // 81920 B (2 CTAs/SM)
    cudaFuncSetAttribute(gemm_pipe<false, __half>, cudaFuncAttributeMaxDynamicSharedMemorySize, SH);
    cudaFuncSetAttribute(gemm_pipe<true,  float >, cudaFuncAttributeMaxDynamicSharedMemorySize, SH);
    cudaFuncSetAttribute(gemm_pipe<false, float >, cudaFuncAttributeMaxDynamicSharedMemorySize, SH);

    // prep (5 launches so ncu -s 5 captures the L1 GEMM)
    pack_kernel<<<4096, 256>>>(motions, angles, z, l5_w);       // + W5 cvt
    cvt_rows<<<dim3(2048, 8), 256>>>(l1_w, W1h, 2048, 2368);
    cvt_rows<<<dim3(2432, 8), 256>>>(l2_w, W2h, 2368, 2048);
    cvt_rows<<<dim3(2048, 1), 256>>>(l3_w, W3h, 2048, 2496);
    cvt_rows<<<dim3(2432, 1), 256>>>(l4_w, W4h, 2368, 2176);

    // L1: H1[e] = fp16(elu(X @ W1[e]^T + b1[e]))   K=2368
    gemm_pipe<false, __half><<<dim3(16, 32, 8), 256, SH>>>(
        X, 2368, (size_t)0,
        W1h, (size_t)2048 * 2368,
        l1_b, 2048, nullptr,
        H1, 2048, (size_t)BROWS * 2048,
        2048, 2368);

    // L2: E2[e] = para[e] * elu(H1[e] @ W2[e]^T + b2[e])   K=2048, N pad 2432
    gemm_pipe<true, float><<<dim3(19, 32, 8), 256, SH>>>(
        H1, 2048, (size_t)BROWS * 2048,
        W2h, (size_t)2432 * 2048,
        l2_b, 2368, para,
        E2, 2368, (size_t)BROWS * 2368,
        2368, 2048);

    // expert sum -> bufC[:, :2368] (fp16)
    reduce_kernel<<<4096, 256>>>();

    // L3: bufD = fp16(elu(bufC @ W3^T + b3))   K=2496
    gemm_pipe<false, __half><<<dim3(16, 32, 1), 256, SH>>>(
        bufC, 2496, (size_t)0, W3h, (size_t)0, l3_b, 0, nullptr,
        bufD, 2176, (size_t)0, 2048, 2496);

    // L4: bufE = fp16(elu(bufD @ W4^T + b4))   K=2176, N pad 2432
    gemm_pipe<false, __half><<<dim3(19, 32, 1), 256, SH>>>(
        bufD, 2176, (size_t)0, W4h, (size_t)0, l4_b, 0, nullptr,
        bufE, 2496, (size_t)0, 2368, 2176);

    // L5: out = elu(bufE @ W5^T + b5)   K=2496, N=256 (fp32 out)
    gemm_pipe<false, float><<<dim3(2, 32, 1), 256, SH>>>(
        bufE, 2496, (size_t)0, W5h, (size_t)0, l5_b, 0, nullptr,
        out, 256, (size_t)0, 256, 2496);
}